// round 1
// baseline (speedup 1.0000x reference)
#include <cuda_runtime.h>
#include <math.h>

#define Bb 8
#define Tt 1024
#define Cc 768
#define Hh 12
#define Dd 64
#define Ll 6
#define Vv 50257

// ---------------- scratch (no allocations allowed) ----------------
__device__ __align__(16) float g_x[Bb * Tt * Cc];        // residual stream
__device__ __align__(16) float g_h[Bb * Tt * Cc];        // ln output
__device__ __align__(16) float g_y[Bb * Tt * Cc];        // attn output
__device__ __align__(16) float g_qkv[Bb * Tt * 3 * Cc];  // qkv
__device__ __align__(16) float g_m[Bb * Tt * 4 * Cc];    // mlp hidden
__device__ __align__(16) float g_xl[Bb * Cc];            // lnf(last pos)

// ---------------- embedding ----------------
__global__ void embed_kernel(const int* __restrict__ idx,
                             const float* __restrict__ wte,
                             const float* __restrict__ wpe) {
    int i = blockIdx.x * blockDim.x + threadIdx.x;
    if (i >= Bb * Tt * Cc) return;
    int c = i % Cc;
    int bt = i / Cc;
    int t = bt % Tt;
    g_x[i] = wte[(long)idx[bt] * Cc + c] + wpe[t * Cc + c];
}

// ---------------- layernorm (one block per row, C=768) ----------------
__global__ __launch_bounds__(256) void ln_kernel(const float* __restrict__ in,
                                                 float* __restrict__ out,
                                                 const float* __restrict__ w,
                                                 const float* __restrict__ b,
                                                 long in_stride, long in_off) {
    int r = blockIdx.x;
    int tid = threadIdx.x;
    const float* xr = in + (long)r * in_stride + in_off;
    float v0 = xr[tid], v1 = xr[tid + 256], v2 = xr[tid + 512];
    __shared__ float red[256];
    red[tid] = v0 + v1 + v2;
    __syncthreads();
    for (int off = 128; off; off >>= 1) {
        if (tid < off) red[tid] += red[tid + off];
        __syncthreads();
    }
    float mean = red[0] * (1.0f / 768.0f);
    __syncthreads();
    float d0 = v0 - mean, d1 = v1 - mean, d2 = v2 - mean;
    red[tid] = d0 * d0 + d1 * d1 + d2 * d2;
    __syncthreads();
    for (int off = 128; off; off >>= 1) {
        if (tid < off) red[tid] += red[tid + off];
        __syncthreads();
    }
    float rstd = rsqrtf(red[0] * (1.0f / 768.0f) + 1e-5f);
    float* orow = out + (long)r * Cc;
    orow[tid]       = d0 * rstd * w[tid]       + b[tid];
    orow[tid + 256] = d1 * rstd * w[tid + 256] + b[tid + 256];
    orow[tid + 512] = d2 * rstd * w[tid + 512] + b[tid + 512];
}

// ---------------- SGEMM: out[m,n] = sum_k A[m,k]*W[n,k] + bias[n] (+res) (+gelu)
// BM=BN=128, BK=8, 256 threads, 8x8 per thread. M,N %128==0, K %8==0.
template <bool GELU, bool RESID>
__global__ __launch_bounds__(256) void sgemm_kernel(
    const float* __restrict__ A, const float* __restrict__ W,
    const float* __restrict__ bias, const float* __restrict__ res,
    float* __restrict__ out, int M, int N, int K) {
    __shared__ float As[8][128];
    __shared__ float Ws[8][128];
    int tid = threadIdx.x;
    int m0 = blockIdx.y * 128;
    int n0 = blockIdx.x * 128;
    int lr = tid >> 1;
    int lc = (tid & 1) * 4;
    int tx = tid & 15, ty = tid >> 4;
    float acc[8][8];
#pragma unroll
    for (int i = 0; i < 8; i++)
#pragma unroll
        for (int j = 0; j < 8; j++) acc[i][j] = 0.0f;

    const float* Ap = A + (long)(m0 + lr) * K + lc;
    const float* Wp = W + (long)(n0 + lr) * K + lc;
    for (int k0 = 0; k0 < K; k0 += 8) {
        float4 a4 = *(const float4*)(Ap + k0);
        float4 w4 = *(const float4*)(Wp + k0);
        __syncthreads();
        As[lc + 0][lr] = a4.x; As[lc + 1][lr] = a4.y;
        As[lc + 2][lr] = a4.z; As[lc + 3][lr] = a4.w;
        Ws[lc + 0][lr] = w4.x; Ws[lc + 1][lr] = w4.y;
        Ws[lc + 2][lr] = w4.z; Ws[lc + 3][lr] = w4.w;
        __syncthreads();
#pragma unroll
        for (int kk = 0; kk < 8; kk++) {
            float ar[8], br[8];
#pragma unroll
            for (int i = 0; i < 8; i++) ar[i] = As[kk][ty * 8 + i];
#pragma unroll
            for (int j = 0; j < 8; j++) br[j] = Ws[kk][tx * 8 + j];
#pragma unroll
            for (int i = 0; i < 8; i++)
#pragma unroll
                for (int j = 0; j < 8; j++) acc[i][j] += ar[i] * br[j];
        }
    }
#pragma unroll
    for (int i = 0; i < 8; i++) {
        int m = m0 + ty * 8 + i;
#pragma unroll
        for (int j = 0; j < 8; j++) {
            int n = n0 + tx * 8 + j;
            float v = acc[i][j] + bias[n];
            if (RESID) v += res[(long)m * N + n];
            if (GELU) v = 0.5f * v * (1.0f + erff(v * 0.70710678118654752f));
            out[(long)m * N + n] = v;
        }
    }
}

// ---------------- fused LIF attention ----------------
// 16 queries per block (16 warps / 512 threads), K/V tiles of 64 rows in smem.
// Pass 1: online softmax max/Z.  Pass 2: recompute s, LIF-gate, renormalize, PV.
__global__ __launch_bounds__(512) void attn_kernel(
    const float* __restrict__ qkv, float* __restrict__ y,
    const float* __restrict__ thr, const float* __restrict__ leak,
    const float* __restrict__ steep) {
    __shared__ float qs[16][64];
    __shared__ float Ks[64][65];
    __shared__ float Vs[64][65];
    __shared__ float modbuf[16][64];

    int b = blockIdx.z, hh = blockIdx.y;
    int q0 = blockIdx.x * 16;
    int tid = threadIdx.x;
    int w = tid >> 5, lane = tid & 31;

    float th = fabsf(thr[hh]) * 0.1f;
    float lk = 1.0f / (1.0f + __expf(-leak[hh]));
    float sp_in = steep[hh];
    float st = (sp_in > 20.0f) ? sp_in : log1pf(__expf(sp_in));

    // load Q tile (16 x 64)
    for (int i = 0; i < 2; i++) {
        int e = tid + i * 512;
        int r = e >> 6, c = e & 63;
        qs[r][c] = qkv[((long)(b * Tt + q0 + r)) * 2304 + hh * 64 + c];
    }
    int qpos = q0 + w;
    int ntiles = (q0 + 15) / 64 + 1;
    const float scale = 0.125f;
    const long kbase = (long)b * Tt * 2304 + 768 + hh * 64;

    // ---- pass 1: max & Z (online, per-lane then warp merge) ----
    float mval = -INFINITY, zval = 0.0f;
    for (int kt = 0; kt < ntiles; kt++) {
        __syncthreads();
        for (int i = 0; i < 8; i++) {
            int e = tid + i * 512;
            int r = e >> 6, c = e & 63;
            Ks[r][c] = qkv[kbase + (long)(kt * 64 + r) * 2304 + c];
        }
        __syncthreads();
#pragma unroll
        for (int jj = 0; jj < 2; jj++) {
            int j = jj * 32 + lane;
            int kpos = kt * 64 + j;
            if (kpos <= qpos) {
                float s = 0.0f;
#pragma unroll
                for (int d = 0; d < 64; d++) s += qs[w][d] * Ks[j][d];
                s *= scale;
                float nm = fmaxf(mval, s);
                zval = zval * __expf(mval - nm) + __expf(s - nm);
                mval = nm;
            }
        }
    }
#pragma unroll
    for (int off = 16; off >= 1; off >>= 1) {
        float m2 = __shfl_xor_sync(0xffffffffu, mval, off);
        float z2 = __shfl_xor_sync(0xffffffffu, zval, off);
        float nm = fmaxf(mval, m2);
        float e1 = (mval == -INFINITY) ? 0.0f : __expf(mval - nm);
        float e2 = (m2 == -INFINITY) ? 0.0f : __expf(m2 - nm);
        zval = zval * e1 + z2 * e2;
        mval = nm;
    }
    float inv_z = 1.0f / zval;

    // ---- pass 2: LIF modulate + PV ----
    float acc0 = 0.0f, acc1 = 0.0f, smod = 0.0f;
    int d0 = lane * 2, d1 = lane * 2 + 1;
    for (int kt = 0; kt < ntiles; kt++) {
        __syncthreads();
        for (int i = 0; i < 8; i++) {
            int e = tid + i * 512;
            int r = e >> 6, c = e & 63;
            long row = kbase + (long)(kt * 64 + r) * 2304 + c;
            Ks[r][c] = qkv[row];
            Vs[r][c] = qkv[row + 768];
        }
        __syncthreads();
#pragma unroll
        for (int jj = 0; jj < 2; jj++) {
            int j = jj * 32 + lane;
            int kpos = kt * 64 + j;
            float mod = 0.0f;
            if (kpos <= qpos) {
                float s = 0.0f;
#pragma unroll
                for (int d = 0; d < 64; d++) s += qs[w][d] * Ks[j][d];
                s *= scale;
                float p = __expf(s - mval) * inv_z;
                float fire = 1.0f / (1.0f + __expf(-st * (p - th)));
                float wg = fire + lk * (1.0f - fire);
                mod = p * wg;
            }
            modbuf[w][j] = mod;
            smod += mod;
        }
        __syncwarp();
#pragma unroll 8
        for (int j = 0; j < 64; j++) {
            float mv = modbuf[w][j];
            acc0 += mv * Vs[j][d0];
            acc1 += mv * Vs[j][d1];
        }
    }
#pragma unroll
    for (int off = 16; off >= 1; off >>= 1)
        smod += __shfl_xor_sync(0xffffffffu, smod, off);
    float inv_s = 1.0f / (smod + 1e-8f);
    long yo = ((long)(b * Tt + qpos)) * Cc + hh * 64;
    y[yo + d0] = acc0 * inv_s;
    y[yo + d1] = acc1 * inv_s;
}

// ---------------- tied lm head: out[r, n] = dot(xl[r,:], wte[n,:]) ----------------
__global__ __launch_bounds__(256) void lmhead_kernel(const float* __restrict__ wte,
                                                     float* __restrict__ out) {
    __shared__ float xs[Bb * Cc];
    int tid = threadIdx.x;
    for (int i = tid; i < Bb * Cc; i += 256) xs[i] = g_xl[i];
    __syncthreads();
    int warp = tid >> 5, lane = tid & 31;
    int n = blockIdx.x * 8 + warp;
    if (n >= Vv) return;
    float acc[Bb];
#pragma unroll
    for (int r = 0; r < Bb; r++) acc[r] = 0.0f;
    const float* wrow = wte + (long)n * Cc;
    for (int k = lane; k < Cc; k += 32) {
        float wv = wrow[k];
#pragma unroll
        for (int r = 0; r < Bb; r++) acc[r] += wv * xs[r * Cc + k];
    }
#pragma unroll
    for (int r = 0; r < Bb; r++)
#pragma unroll
        for (int off = 16; off >= 1; off >>= 1)
            acc[r] += __shfl_xor_sync(0xffffffffu, acc[r], off);
    if (lane == 0) {
#pragma unroll
        for (int r = 0; r < Bb; r++) out[(long)r * Vv + n] = acc[r];
    }
}

// ---------------- lnf into g_xl (8 last-position rows) ----------------
// reuse ln_kernel with stride Tt*Cc and offset (Tt-1)*Cc.

extern "C" void kernel_launch(void* const* d_in, const int* in_sizes, int n_in,
                              void* d_out, int out_size) {
    const int* idx      = (const int*)d_in[0];
    const float* wte    = (const float*)d_in[1];
    const float* wpe    = (const float*)d_in[2];
    const float* ln1_w  = (const float*)d_in[3];
    const float* ln1_b  = (const float*)d_in[4];
    const float* attn_w = (const float*)d_in[5];
    const float* attn_b = (const float*)d_in[6];
    const float* proj_w = (const float*)d_in[7];
    const float* proj_b = (const float*)d_in[8];
    const float* thr    = (const float*)d_in[9];
    const float* leak   = (const float*)d_in[10];
    const float* steep  = (const float*)d_in[11];
    const float* ln2_w  = (const float*)d_in[12];
    const float* ln2_b  = (const float*)d_in[13];
    const float* fc_w   = (const float*)d_in[14];
    const float* fc_b   = (const float*)d_in[15];
    const float* mproj_w= (const float*)d_in[16];
    const float* mproj_b= (const float*)d_in[17];
    const float* lnf_w  = (const float*)d_in[18];
    const float* lnf_b  = (const float*)d_in[19];
    float* out = (float*)d_out;

    float *px, *ph, *py, *pqkv, *pm, *pxl;
    cudaGetSymbolAddress((void**)&px, g_x);
    cudaGetSymbolAddress((void**)&ph, g_h);
    cudaGetSymbolAddress((void**)&py, g_y);
    cudaGetSymbolAddress((void**)&pqkv, g_qkv);
    cudaGetSymbolAddress((void**)&pm, g_m);
    cudaGetSymbolAddress((void**)&pxl, g_xl);

    const int Mrows = Bb * Tt;  // 8192

    embed_kernel<<<(Bb * Tt * Cc + 255) / 256, 256>>>(idx, wte, wpe);

    for (int l = 0; l < Ll; l++) {
        // ln1
        ln_kernel<<<Mrows, 256>>>(px, ph, ln1_w + l * Cc, ln1_b + l * Cc, Cc, 0);
        // qkv = h @ attn_w^T + attn_b
        {
            dim3 grid(3 * Cc / 128, Mrows / 128);
            sgemm_kernel<false, false><<<grid, 256>>>(
                ph, attn_w + (long)l * 3 * Cc * Cc, attn_b + l * 3 * Cc,
                nullptr, pqkv, Mrows, 3 * Cc, Cc);
        }
        // attention
        {
            dim3 grid(Tt / 16, Hh, Bb);
            attn_kernel<<<grid, 512>>>(pqkv, py, thr + l * Hh, leak + l * Hh,
                                       steep + l * Hh);
        }
        // x = x + y @ proj_w^T + proj_b
        {
            dim3 grid(Cc / 128, Mrows / 128);
            sgemm_kernel<false, true><<<grid, 256>>>(
                py, proj_w + (long)l * Cc * Cc, proj_b + l * Cc, px, px,
                Mrows, Cc, Cc);
        }
        // ln2
        ln_kernel<<<Mrows, 256>>>(px, ph, ln2_w + l * Cc, ln2_b + l * Cc, Cc, 0);
        // m = gelu(h @ fc_w^T + fc_b)
        {
            dim3 grid(4 * Cc / 128, Mrows / 128);
            sgemm_kernel<true, false><<<grid, 256>>>(
                ph, fc_w + (long)l * 4 * Cc * Cc, fc_b + l * 4 * Cc, nullptr,
                pm, Mrows, 4 * Cc, Cc);
        }
        // x = x + m @ mproj_w^T + mproj_b
        {
            dim3 grid(Cc / 128, Mrows / 128);
            sgemm_kernel<false, true><<<grid, 256>>>(
                pm, mproj_w + (long)l * Cc * 4 * Cc, mproj_b + l * Cc, px, px,
                Mrows, Cc, 4 * Cc);
        }
    }

    // lnf on last position of each batch row
    ln_kernel<<<Bb, 256>>>(px, pxl, lnf_w, lnf_b, (long)Tt * Cc,
                           (long)(Tt - 1) * Cc);
    // logits = xl @ wte^T
    lmhead_kernel<<<(Vv + 7) / 8, 256>>>(wte, out);
}